// round 2
// baseline (speedup 1.0000x reference)
#include <cuda_runtime.h>
#include <cuda_bf16.h>

#define N_NODES 50000
#define N_EDGES 800000
#define D_IN    96
#define D_EDGE  32
#define D_OUT   96
#define N_TYPES 4

typedef unsigned long long ull;

// pack two f32 into a b64 register pair
#define PACKF2(dst, lo, hi) \
    asm("mov.b64 %0, {%1, %2};" : "=l"(dst) : "f"(lo), "f"(hi))
#define UNPACKF2(lo, hi, src) \
    asm("mov.b64 {%0, %1}, %2;" : "=f"(lo), "=f"(hi) : "l"(src))
// packed dual-FMA: acc.lo += a.lo*b.lo ; acc.hi += a.hi*b.hi
#define FFMA2(acc, a, b) \
    asm("fma.rn.f32x2 %0, %1, %2, %0;" : "+l"(acc) : "l"(a), "l"(b))

// Scratch: y[t][n][j] = 0.25 * (x[n] @ W_x[t] + b[t])   (76.8 MB, L2-resident)
__device__ float g_y[(size_t)N_TYPES * N_NODES * D_OUT];

// ---------------------------------------------------------------------------
// Kernel A: y[t][n] = 0.25*(x[n] @ W_x[t] + b[t]), node-pair packed FFMA2.
// Grid: (ceil(N/64), 4). Block: 256 threads; each warp owns 8 nodes (4 pairs).
// ---------------------------------------------------------------------------
__global__ __launch_bounds__(256) void precompute_y_kernel(
    const float* __restrict__ x,      // [N, 96]
    const float* __restrict__ W,      // [4, 128, 96]
    const float* __restrict__ b)      // [4, 96]
{
    const int t     = blockIdx.y;
    const int node0 = blockIdx.x * 64;

    __shared__ float Wsm[D_IN][D_OUT];              // 36 KB  (0.25 * W_x[t])
    __shared__ __align__(8) float xs_t[D_IN][64];   // 24 KB  transposed x tile
    __shared__ float bsm[D_OUT];

    const float* Wt = W + (size_t)t * 128 * 96;
    for (int i = threadIdx.x; i < D_IN * D_OUT; i += blockDim.x)
        (&Wsm[0][0])[i] = 0.25f * Wt[i];
    if (threadIdx.x < D_OUT)
        bsm[threadIdx.x] = 0.25f * b[t * D_OUT + threadIdx.x];
    // transposed fill: thread keeps a fixed node-row (L1-resident global line),
    // consecutive threads -> consecutive smem addresses (conflict-free STS)
    for (int i = threadIdx.x; i < D_IN * 64; i += blockDim.x) {
        int c = i >> 6, r = i & 63;
        int n = node0 + r;
        xs_t[c][r] = (n < N_NODES) ? x[(size_t)n * D_IN + c] : 0.0f;
    }
    __syncthreads();

    const int wid  = threadIdx.x >> 5;
    const int lane = threadIdx.x & 31;
    const int i0   = wid * 8;                     // first node (of 8) this warp

    ull acc[4][3];
    {
        float b0 = bsm[lane], b1 = bsm[lane + 32], b2 = bsm[lane + 64];
        ull B0, B1, B2;
        PACKF2(B0, b0, b0); PACKF2(B1, b1, b1); PACKF2(B2, b2, b2);
#pragma unroll
        for (int p = 0; p < 4; p++) { acc[p][0] = B0; acc[p][1] = B1; acc[p][2] = B2; }
    }

#pragma unroll 8
    for (int k = 0; k < D_IN; k++) {
        float w0 = Wsm[k][lane];
        float w1 = Wsm[k][lane + 32];
        float w2 = Wsm[k][lane + 64];
        ull W0, W1, W2;
        PACKF2(W0, w0, w0); PACKF2(W1, w1, w1); PACKF2(W2, w2, w2);
#pragma unroll
        for (int p = 0; p < 4; p++) {
            ull xv2 = *reinterpret_cast<const ull*>(&xs_t[k][i0 + 2 * p]);
            FFMA2(acc[p][0], xv2, W0);
            FFMA2(acc[p][1], xv2, W1);
            FFMA2(acc[p][2], xv2, W2);
        }
    }

#pragma unroll
    for (int p = 0; p < 4; p++) {
        int n_lo = node0 + i0 + 2 * p;
        int n_hi = n_lo + 1;
#pragma unroll
        for (int c = 0; c < 3; c++) {
            float lo, hi;
            UNPACKF2(lo, hi, acc[p][c]);
            if (n_lo < N_NODES)
                g_y[((size_t)t * N_NODES + n_lo) * D_OUT + lane + 32 * c] = lo;
            if (n_hi < N_NODES)
                g_y[((size_t)t * N_NODES + n_hi) * D_OUT + lane + 32 * c] = hi;
        }
    }
}

// ---------------------------------------------------------------------------
// Kernel B: edge kernel, edge-pair packed FFMA2.
// Each block handles one relation type (blockIdx.y); warps compact their
// matching edges (ballot+rank) into a queue and process batches of 8 edges
// (4 packed pairs).  out[dst] += y[t][src] + 0.25 * (|ef[s]-ef[d]| @ W_e[t])
// ---------------------------------------------------------------------------
#define EK_WARPS   8
#define BATCH      8
#define QCAP       40
#define ESM_STRIDE 10   // pad: 2-way max STS conflict, 8B-aligned pair reads

__global__ __launch_bounds__(256) void edge_kernel(
    const float* __restrict__ ef,     // [N, 32]
    const int*   __restrict__ src,    // [E]
    const int*   __restrict__ dst,    // [E]
    const int*   __restrict__ et,     // [E]
    const float* __restrict__ W,      // [4, 128, 96]
    float*       __restrict__ out)    // [N, 96]
{
    const int t = blockIdx.y;

    __shared__ __align__(8) float2 Wdup[D_EDGE][D_OUT];           // 24 KB (w,w) dup
    __shared__ int   eidx[EK_WARPS][QCAP];
    __shared__ __align__(8) float esm[EK_WARPS][D_EDGE][ESM_STRIDE]; // 10 KB

    // rows 96..127 of W[t] = W_e, pre-scaled by 1/4, duplicated into both halves
    const float* Wt = W + (size_t)t * 128 * 96 + 96 * 96;
    for (int i = threadIdx.x; i < D_EDGE * D_OUT; i += blockDim.x) {
        float w = 0.25f * Wt[i];
        (&Wdup[0][0])[i] = make_float2(w, w);
    }
    __syncthreads();

    const int wid  = threadIdx.x >> 5;
    const int lane = threadIdx.x & 31;
    const unsigned lanemask_lt = (1u << lane) - 1u;

    const long gw     = (long)blockIdx.x * EK_WARPS + wid;
    const long stride = (long)gridDim.x * EK_WARPS * 32;

    long base = gw * 32;
    int  q    = 0;

    while (true) {
        while (q < BATCH && base < N_EDGES) {
            long eid = base + lane;
            bool ok  = (eid < N_EDGES) && (et[eid] == t);
            unsigned m = __ballot_sync(0xffffffffu, ok);
            int rank = __popc(m & lanemask_lt);
            if (ok) eidx[wid][q + rank] = (int)eid;
            q    += __popc(m);
            base += stride;
        }
        __syncwarp();
        if (q == 0) break;

        const int B = (q < BATCH) ? q : BATCH;   // warp-uniform

        int s[BATCH], d[BATCH];
        // fill |ef[s]-ef[d]| k-major: lane writes its k=lane element per edge
#pragma unroll
        for (int i = 0; i < BATCH; i++) {
            int e2 = (i < B) ? eidx[wid][i] : eidx[wid][0];
            s[i] = src[e2];
            d[i] = dst[e2];
            float a  = ef[(size_t)s[i] * D_EDGE + lane];
            float bb = ef[(size_t)d[i] * D_EDGE + lane];
            esm[wid][lane][i] = fabsf(a - bb);
        }
        __syncwarp();

        // gather y[t][src] into packed (edge2p, edge2p+1) accumulators
        ull acc[4][3];
#pragma unroll
        for (int p = 0; p < 4; p++) {
            const float* y0 = g_y + ((size_t)t * N_NODES + s[2 * p])     * D_OUT;
            const float* y1 = g_y + ((size_t)t * N_NODES + s[2 * p + 1]) * D_OUT;
#pragma unroll
            for (int c = 0; c < 3; c++) {
                float lo = y0[lane + 32 * c];
                float hi = y1[lane + 32 * c];
                PACKF2(acc[p][c], lo, hi);
            }
        }

#pragma unroll 8
        for (int k = 0; k < D_EDGE; k++) {
            ull W0 = *reinterpret_cast<const ull*>(&Wdup[k][lane]);
            ull W1 = *reinterpret_cast<const ull*>(&Wdup[k][lane + 32]);
            ull W2 = *reinterpret_cast<const ull*>(&Wdup[k][lane + 64]);
#pragma unroll
            for (int p = 0; p < 4; p++) {
                ull ev2 = *reinterpret_cast<const ull*>(&esm[wid][k][2 * p]);
                FFMA2(acc[p][0], ev2, W0);
                FFMA2(acc[p][1], ev2, W1);
                FFMA2(acc[p][2], ev2, W2);
            }
        }

#pragma unroll
        for (int p = 0; p < 4; p++) {
            float* o0 = out + (size_t)d[2 * p]     * D_OUT;
            float* o1 = out + (size_t)d[2 * p + 1] * D_OUT;
#pragma unroll
            for (int c = 0; c < 3; c++) {
                float lo, hi;
                UNPACKF2(lo, hi, acc[p][c]);
                if (2 * p     < B) atomicAdd(o0 + lane + 32 * c, lo);
                if (2 * p + 1 < B) atomicAdd(o1 + lane + 32 * c, hi);
            }
        }

        // slide remainder (<8) to queue front
        int rem = q - B;
        int tmp = 0;
        __syncwarp();
        if (lane < rem) tmp = eidx[wid][B + lane];
        __syncwarp();
        if (lane < rem) eidx[wid][lane] = tmp;
        __syncwarp();
        q = rem;
    }
}

// ---------------------------------------------------------------------------
extern "C" void kernel_launch(void* const* d_in, const int* in_sizes, int n_in,
                              void* d_out, int out_size)
{
    const float* x   = (const float*)d_in[0];          // [N, 96]
    const float* ef  = (const float*)d_in[1];          // [N, 32]
    const int*   ei  = (const int*)  d_in[2];          // [2, E]
    const int*   et  = (const int*)  d_in[3];          // [E]
    const float* W   = (const float*)d_in[4];          // [4, 128, 96]
    const float* b   = (const float*)d_in[5];          // [4, 96]
    float*       out = (float*)d_out;                  // [N, 96]

    const int* srcp = ei;
    const int* dstp = ei + N_EDGES;

    cudaMemsetAsync(out, 0, (size_t)out_size * sizeof(float), 0);

    {
        dim3 grid((N_NODES + 63) / 64, N_TYPES);
        precompute_y_kernel<<<grid, 256>>>(x, W, b);
    }
    {
        dim3 grid(296, N_TYPES);
        edge_kernel<<<grid, 256>>>(ef, srcp, dstp, et, W, out);
    }
}